// round 12
// baseline (speedup 1.0000x reference)
#include <cuda_runtime.h>
#include <cuda_bf16.h>
#include <math.h>
#include <stdint.h>

// Problem constants
#define BB 2
#define TT 1024
#define DD 2048
#define HH 16
#define DHD 128
#define RR (BB*TT)       // 2048
#define DHALF (DD/2)     // 1024
#define LCH 128
#define NC (TT/LCH)
#define BD (BB*DD)

#define KDIM 2048
#define NCHUNK (KDIM/32)                      // 64 chunks of 32 bf16 (64B rows)
#define STAGE_BYTES 24576                     // A hi/lo 4K+4K, B hi/lo 8K+8K
#define SMEM_GEMM (4*STAGE_BYTES + 1024)      // 4 stages, ~97KB -> 2 CTAs/SM
#define SMEM_FLASH (65536 + 2*65536 + 1024)   // Q + 2 KV stages

// -------- fp32 scratch --------
__device__ float g_hdn[RR*DHALF];
__device__ float g_l2[RR*DD];
__device__ float g_fin[NC*BD];
__device__ float g_carry[NC*BD];

// -------- bf16 hi/lo scratch --------
__device__ __nv_bfloat16 g_xhi[RR*DD],  g_xlo[RR*DD];
__device__ __nv_bfloat16 g_qhi[RR*DD],  g_qlo[RR*DD];
__device__ __nv_bfloat16 g_fhi[RR*DD],  g_flo[RR*DD];
__device__ __nv_bfloat16 g_ahi[RR*DD],  g_alo[RR*DD];
__device__ __nv_bfloat16 g_khhi[RR*DD], g_khlo[RR*DD];   // [b,h,t,dh]
__device__ __nv_bfloat16 g_vhhi[RR*DD], g_vhlo[RR*DD];   // [b,h,t,dh]
__device__ __nv_bfloat16 g_wqhi[DD*DD], g_wqlo[DD*DD];
__device__ __nv_bfloat16 g_wkhi[DD*DD], g_wklo[DD*DD];
__device__ __nv_bfloat16 g_wvhi[DD*DD], g_wvlo[DD*DD];
__device__ __nv_bfloat16 g_wohi[DD*DD], g_wolo[DD*DD];
__device__ __nv_bfloat16 g_r1hi[DHALF*DD], g_r1lo[DHALF*DD];

// ================= PTX helpers =================
__device__ __forceinline__ uint32_t smem_u32(const void* p) {
    uint32_t a;
    asm("{ .reg .u64 t; cvta.to.shared.u64 t, %1; cvt.u32.u64 %0, t; }" : "=r"(a) : "l"(p));
    return a;
}
__device__ __forceinline__ void cpasync16(uint32_t s, const void* g) {
    asm volatile("cp.async.cg.shared.global [%0], [%1], 16;" :: "r"(s), "l"(g));
}
#define CP_COMMIT() asm volatile("cp.async.commit_group;" ::: "memory")
#define CP_WAIT(n)  asm volatile("cp.async.wait_group %0;" :: "n"(n) : "memory")

__device__ __forceinline__ void ldsm4(uint32_t* r, uint32_t addr) {
    asm volatile("ldmatrix.sync.aligned.m8n8.x4.shared.b16 {%0,%1,%2,%3}, [%4];"
        : "=r"(r[0]), "=r"(r[1]), "=r"(r[2]), "=r"(r[3]) : "r"(addr));
}
__device__ __forceinline__ void ldsm4t(uint32_t* r, uint32_t addr) {
    asm volatile("ldmatrix.sync.aligned.m8n8.x4.trans.shared.b16 {%0,%1,%2,%3}, [%4];"
        : "=r"(r[0]), "=r"(r[1]), "=r"(r[2]), "=r"(r[3]) : "r"(addr));
}
__device__ __forceinline__ void mma16816(float* c, const uint32_t* a, const uint32_t* b) {
    asm volatile(
        "mma.sync.aligned.m16n8k16.row.col.f32.bf16.bf16.f32 "
        "{%0,%1,%2,%3}, {%4,%5,%6,%7}, {%8,%9}, {%0,%1,%2,%3};"
        : "+f"(c[0]), "+f"(c[1]), "+f"(c[2]), "+f"(c[3])
        : "r"(a[0]), "r"(a[1]), "r"(a[2]), "r"(a[3]), "r"(b[0]), "r"(b[1]));
}
__device__ __forceinline__ void pack_hilo(float x, float y, uint32_t& hi, uint32_t& lo) {
    __nv_bfloat16 hx = __float2bfloat16(x), hy = __float2bfloat16(y);
    __nv_bfloat16 lx = __float2bfloat16(x - __bfloat162float(hx));
    __nv_bfloat16 ly = __float2bfloat16(y - __bfloat162float(hy));
    __nv_bfloat162 hp(hx, hy), lp(lx, ly);
    hi = *(uint32_t*)&hp; lo = *(uint32_t*)&lp;
}

// ================= fp32 -> bf16 hi/lo split (merged, 6 tensors) ============
struct CvtArgs {
    const float4* src[6];
    __nv_bfloat162* hi[6];
    __nv_bfloat162* lo[6];
    int n4[6];
};
__global__ void cvt_split_all(CvtArgs a) {
    int t = blockIdx.y;
    int i = blockIdx.x * blockDim.x + threadIdx.x;
    if (i >= a.n4[t]) return;
    float4 v = a.src[t][i];
    __nv_bfloat16 h0 = __float2bfloat16(v.x), h1 = __float2bfloat16(v.y);
    __nv_bfloat16 h2 = __float2bfloat16(v.z), h3 = __float2bfloat16(v.w);
    __nv_bfloat16 l0 = __float2bfloat16(v.x - __bfloat162float(h0));
    __nv_bfloat16 l1 = __float2bfloat16(v.y - __bfloat162float(h1));
    __nv_bfloat16 l2 = __float2bfloat16(v.z - __bfloat162float(h2));
    __nv_bfloat16 l3 = __float2bfloat16(v.w - __bfloat162float(h3));
    a.hi[t][2*i]   = __nv_bfloat162(h0, h1);
    a.hi[t][2*i+1] = __nv_bfloat162(h2, h3);
    a.lo[t][2*i]   = __nv_bfloat162(l0, l1);
    a.lo[t][2*i+1] = __nv_bfloat162(l2, l3);
}

// ================= HMMA GEMM: C = A * B^T (split bf16, fp32 acc) ===========
// 64x128 CTA tile, 128 threads (2x2 warps of 32x64), BK=32 (64B rows),
// 4-stage cp.async pipeline with ONE __syncthreads per chunk, 2 CTAs/SM.
// 64B-row swizzle: chunk j in row m stored at j ^ ((m>>1)&3).
// MODE 0: fp32 plain   MODE 1: bias+silu fp32
// MODE 4: bf16 hi/lo plain   MODE 5: fp32 scatter + bf16 hi/lo scatter [b,h,t,dh]
template<int MODE>
__global__ void __launch_bounds__(128, 2)
gemm_mma(const __nv_bfloat16* __restrict__ Ahi, const __nv_bfloat16* __restrict__ Alo,
         const __nv_bfloat16* __restrict__ Bhi, const __nv_bfloat16* __restrict__ Blo,
         float* __restrict__ C, __nv_bfloat16* __restrict__ Chi,
         __nv_bfloat16* __restrict__ Clo, int ldc, const float* __restrict__ bias) {
    extern __shared__ char dsm[];
    const int tid  = threadIdx.x;
    const int wid  = tid >> 5, lane = tid & 31;
    const int m0   = blockIdx.y * 64, n0 = blockIdx.x * 128;
    const int wm   = (wid & 1) * 32;
    const int wn   = (wid >> 1) * 64;
    uint32_t sb = (smem_u32(dsm) + 1023u) & ~1023u;

    const char* gA0 = (const char*)(Ahi + (size_t)m0 * KDIM);
    const char* gA1 = (const char*)(Alo + (size_t)m0 * KDIM);
    const char* gB0 = (const char*)(Bhi + (size_t)n0 * KDIM);
    const char* gB1 = (const char*)(Blo + (size_t)n0 * KDIM);

    // stage layout: Ahi@0(4K) Alo@4K Bhi@8K(8K) Blo@16K(8K)
    auto load_stage = [&](int s, int c) {
        uint32_t base = sb + (uint32_t)s * STAGE_BYTES;
        const int kb = c * 64;   // byte offset in K
        #pragma unroll
        for (int it = 0; it < 2; it++) {
            int idx = tid + it * 128;                  // 0..255 : A rows 0..63, j 0..3
            int m = idx >> 2, j = idx & 3;
            uint32_t off = (uint32_t)m * 64u + (uint32_t)((j ^ ((m >> 1) & 3)) << 4);
            size_t go = (size_t)m * (KDIM * 2) + kb + j * 16;
            cpasync16(base + off,         gA0 + go);
            cpasync16(base + 4096u + off, gA1 + go);
        }
        #pragma unroll
        for (int it = 0; it < 4; it++) {
            int idx = tid + it * 128;                  // 0..511 : B rows 0..127
            int m = idx >> 2, j = idx & 3;
            uint32_t off = (uint32_t)m * 64u + (uint32_t)((j ^ ((m >> 1) & 3)) << 4);
            size_t go = (size_t)m * (KDIM * 2) + kb + j * 16;
            cpasync16(base + 8192u  + off, gB0 + go);
            cpasync16(base + 16384u + off, gB1 + go);
        }
        CP_COMMIT();
    };

    float acc[2][8][4];
    #pragma unroll
    for (int i = 0; i < 2; i++)
        #pragma unroll
        for (int j = 0; j < 8; j++)
            #pragma unroll
            for (int r = 0; r < 4; r++) acc[i][j][r] = 0.f;

    const int aRow0 = wm + ((lane >> 3) & 1) * 8 + (lane & 7);
    const int aKh   = (lane >> 4) & 1;
    const int bRow0 = wn + ((lane >> 4) & 1) * 8 + (lane & 7);
    const int bKh   = (lane >> 3) & 1;

    load_stage(0, 0);
    load_stage(1, 1);
    load_stage(2, 2);

    #pragma unroll 1
    for (int c = 0; c < NCHUNK; c++) {
        int rem = NCHUNK - 1 - c;
        if (rem >= 2)      { CP_WAIT(2); }
        else if (rem == 1) { CP_WAIT(1); }
        else               { CP_WAIT(0); }
        __syncthreads();
        if (c + 3 < NCHUNK) load_stage((c + 3) & 3, c + 3);

        uint32_t base = sb + (uint32_t)(c & 3) * STAGE_BYTES;
        #pragma unroll
        for (int kk = 0; kk < 2; kk++) {
            uint32_t ah[2][4], al[2][4], bh[4][4], bl[4][4];
            #pragma unroll
            for (int mt = 0; mt < 2; mt++) {
                int row = aRow0 + mt * 16;
                int cc = (kk * 2 + aKh) ^ ((row >> 1) & 3);
                uint32_t off = (uint32_t)row * 64u + (uint32_t)cc * 16u;
                ldsm4(ah[mt], base + off);
                ldsm4(al[mt], base + 4096u + off);
            }
            #pragma unroll
            for (int g = 0; g < 4; g++) {
                int row = bRow0 + g * 16;
                int cc = (kk * 2 + bKh) ^ ((row >> 1) & 3);
                uint32_t off = (uint32_t)row * 64u + (uint32_t)cc * 16u;
                ldsm4(bh[g], base + 8192u  + off);
                ldsm4(bl[g], base + 16384u + off);
            }
            #pragma unroll
            for (int i = 0; i < 2; i++)
                #pragma unroll
                for (int j = 0; j < 8; j++) {
                    const uint32_t* bph = &bh[j >> 1][(j & 1) * 2];
                    const uint32_t* bpl = &bl[j >> 1][(j & 1) * 2];
                    mma16816(acc[i][j], ah[i], bph);
                    mma16816(acc[i][j], ah[i], bpl);
                    mma16816(acc[i][j], al[i], bph);
                }
        }
    }

    #pragma unroll
    for (int i = 0; i < 2; i++) {
        #pragma unroll
        for (int j = 0; j < 8; j++) {
            #pragma unroll
            for (int r = 0; r < 4; r++) {
                int row = m0 + wm + i * 16 + (lane >> 2) + (r >> 1) * 8;
                int col = n0 + wn + j * 8 + (lane & 3) * 2 + (r & 1);
                float v = acc[i][j][r];
                if (MODE == 0) {
                    C[(size_t)row * ldc + col] = v;
                } else if (MODE == 1) {
                    v += bias[col];
                    v = v / (1.f + expf(-v));
                    C[(size_t)row * ldc + col] = v;
                } else if (MODE == 4) {
                    __nv_bfloat16 hv = __float2bfloat16(v);
                    size_t idx = (size_t)row * ldc + col;
                    Chi[idx] = hv;
                    Clo[idx] = __float2bfloat16(v - __bfloat162float(hv));
                } else {  // MODE 5
                    int b = row >> 10, t = row & 1023;
                    int h = col >> 7,  jj = col & 127;
                    size_t idx = (((size_t)(b * HH + h)) * TT + t) * DHD + jj;
                    C[idx] = v;
                    __nv_bfloat16 hv = __float2bfloat16(v);
                    Chi[idx] = hv;
                    Clo[idx] = __float2bfloat16(v - __bfloat162float(hv));
                }
            }
        }
    }
}

// ================= flash attention (fused S, softmax, PV) ==================
__global__ void __launch_bounds__(256, 1)
flash_attn(const __nv_bfloat16* __restrict__ khhi, const __nv_bfloat16* __restrict__ khlo,
           const __nv_bfloat16* __restrict__ vhhi, const __nv_bfloat16* __restrict__ vhlo) {
    extern __shared__ char dsm[];
    const int z  = blockIdx.x;
    const int qi = (int)gridDim.y - 1 - (int)blockIdx.y;
    const int b = z >> 4, h = z & 15;
    const int m0 = qi * 128;
    const int tid = threadIdx.x, wid = tid >> 5, lane = tid & 31;
    uint32_t sb = (smem_u32(dsm) + 1023u) & ~1023u;
    const uint32_t qs = sb;

    {
        const __nv_bfloat16* Qh = g_qhi + ((size_t)(b * TT) + m0) * DD + h * DHD;
        const __nv_bfloat16* Ql = g_qlo + ((size_t)(b * TT) + m0) * DD + h * DHD;
        #pragma unroll
        for (int it = 0; it < 8; it++) {
            int idx = tid + it * 256;
            int row = idx >> 4, u = idx & 15;
            uint32_t sa = qs + (uint32_t)row * 256u + (uint32_t)((u ^ (row & 7)) << 4);
            cpasync16(sa,           Qh + (size_t)row * DD + u * 8);
            cpasync16(sa + 32768u,  Ql + (size_t)row * DD + u * 8);
        }
    }
    const __nv_bfloat16* Kh = khhi + (size_t)z * TT * DHD;
    const __nv_bfloat16* Kl = khlo + (size_t)z * TT * DHD;
    const __nv_bfloat16* Vh = vhhi + (size_t)z * TT * DHD;
    const __nv_bfloat16* Vl = vhlo + (size_t)z * TT * DHD;

    auto load_kv = [&](int s, int ch) {
        uint32_t base = sb + 65536u + (uint32_t)s * 65536u;
        const __nv_bfloat16* srcs[4] = {
            Kh + (size_t)ch * 64 * DHD, Kl + (size_t)ch * 64 * DHD,
            Vh + (size_t)ch * 64 * DHD, Vl + (size_t)ch * 64 * DHD };
        #pragma unroll
        for (int tI = 0; tI < 4; tI++) {
            uint32_t tb = base + (uint32_t)tI * 16384u;
            const __nv_bfloat16* g = srcs[tI];
            #pragma unroll
            for (int it = 0; it < 4; it++) {
                int idx = tid + it * 256;
                int row = idx >> 4, u = idx & 15;
                cpasync16(tb + (uint32_t)row * 256u + (uint32_t)((u ^ (row & 7)) << 4),
                          g + (size_t)row * DHD + u * 8);
            }
        }
        CP_COMMIT();
    };

    const int nch = 2 * qi + 2;
    load_kv(0, 0);

    float m_[2] = {-1e30f, -1e30f}, l_[2] = {0.f, 0.f};
    float oacc[16][4];
    #pragma unroll
    for (int j = 0; j < 16; j++)
        #pragma unroll
        for (int r = 0; r < 4; r++) oacc[j][r] = 0.f;

    const int qrow_lo = wid * 16 + (lane >> 2);
    const float scale = 0.08838834764831845f;

    #pragma unroll 1
    for (int ch = 0; ch < nch; ch++) {
        if (ch + 1 < nch) {
            load_kv((ch + 1) & 1, ch + 1);
            CP_WAIT(1);
        } else {
            CP_WAIT(0);
        }
        __syncthreads();
        uint32_t kb = sb + 65536u + (uint32_t)(ch & 1) * 65536u;
        uint32_t vb = kb + 32768u;

        float sacc[8][4];
        #pragma unroll
        for (int j = 0; j < 8; j++)
            #pragma unroll
            for (int r = 0; r < 4; r++) sacc[j][r] = 0.f;

        #pragma unroll
        for (int kk = 0; kk < 8; kk++) {
            uint32_t ah[4], al[4];
            int arow = wid * 16 + ((lane >> 3) & 1) * 8 + (lane & 7);
            int au = (kk * 2 + ((lane >> 4) & 1)) ^ (arow & 7);
            uint32_t aoff = (uint32_t)arow * 256u + (uint32_t)au * 16u;
            ldsm4(ah, qs + aoff);
            ldsm4(al, qs + 32768u + aoff);
            #pragma unroll
            for (int g = 0; g < 4; g++) {
                uint32_t bh_[4], bl_[4];
                int brow = g * 16 + ((lane >> 4) & 1) * 8 + (lane & 7);
                int bu = (kk * 2 + ((lane >> 3) & 1)) ^ (brow & 7);
                uint32_t boff = (uint32_t)brow * 256u + (uint32_t)bu * 16u;
                ldsm4(bh_, kb + boff);
                ldsm4(bl_, kb + 16384u + boff);
                #pragma unroll
                for (int jj = 0; jj < 2; jj++) {
                    int j = g * 2 + jj;
                    mma16816(sacc[j], ah, &bh_[jj * 2]);
                    mma16816(sacc[j], ah, &bl_[jj * 2]);
                    mma16816(sacc[j], al, &bh_[jj * 2]);
                }
            }
        }

        const int kvbase = ch * 64;
        const bool maskp = (kvbase + 63 > m0);
        float mx[2] = {-1e30f, -1e30f};
        #pragma unroll
        for (int j = 0; j < 8; j++)
            #pragma unroll
            for (int r = 0; r < 4; r++) {
                float v = sacc[j][r] * scale;
                if (maskp) {
                    int col_g = kvbase + 8 * j + 2 * (lane & 3) + (r & 1);
                    int row_g = m0 + qrow_lo + (r >> 1) * 8;
                    if (col_g > row_g) v = -1e30f;
                }
                sacc[j][r] = v;
                mx[r >> 1] = fmaxf(mx[r >> 1], v);
            }
        #pragma unroll
        for (int rr = 0; rr < 2; rr++) {
            mx[rr] = fmaxf(mx[rr], __shfl_xor_sync(0xffffffffu, mx[rr], 1));
            mx[rr] = fmaxf(mx[rr], __shfl_xor_sync(0xffffffffu, mx[rr], 2));
        }
        float mn0 = fmaxf(m_[0], mx[0]), mn1 = fmaxf(m_[1], mx[1]);
        float al0 = __expf(m_[0] - mn0), al1 = __expf(m_[1] - mn1);
        float rs[2] = {0.f, 0.f};
        #pragma unroll
        for (int j = 0; j < 8; j++)
            #pragma unroll
            for (int r = 0; r < 4; r++) {
                float p = __expf(sacc[j][r] - ((r >> 1) ? mn1 : mn0));
                sacc[j][r] = p;
                rs[r >> 1] += p;
            }
        #pragma unroll
        for (int rr = 0; rr < 2; rr++) {
            rs[rr] += __shfl_xor_sync(0xffffffffu, rs[rr], 1);
            rs[rr] += __shfl_xor_sync(0xffffffffu, rs[rr], 2);
        }
        l_[0] = l_[0] * al0 + rs[0];
        l_[1] = l_[1] * al1 + rs[1];
        m_[0] = mn0; m_[1] = mn1;
        #pragma unroll
        for (int j = 0; j < 16; j++) {
            oacc[j][0] *= al0; oacc[j][1] *= al0;
            oacc[j][2] *= al1; oacc[j][3] *= al1;
        }

        #pragma unroll
        for (int kk = 0; kk < 4; kk++) {
            uint32_t aph[4], apl[4];
            pack_hilo(sacc[2*kk][0],   sacc[2*kk][1],   aph[0], apl[0]);
            pack_hilo(sacc[2*kk][2],   sacc[2*kk][3],   aph[1], apl[1]);
            pack_hilo(sacc[2*kk+1][0], sacc[2*kk+1][1], aph[2], apl[2]);
            pack_hilo(sacc[2*kk+1][2], sacc[2*kk+1][3], aph[3], apl[3]);
            int krow = kk * 16 + ((lane >> 3) & 1) * 8 + (lane & 7);
            #pragma unroll
            for (int ng = 0; ng < 8; ng++) {
                int nchk = ng * 2 + (lane >> 4);
                uint32_t addr = vb + (uint32_t)krow * 256u
                              + (uint32_t)((nchk ^ (krow & 7)) << 4);
                uint32_t bvh[4], bvl[4];
                ldsm4t(bvh, addr);
                ldsm4t(bvl, addr + 16384u);
                #pragma unroll
                for (int jj = 0; jj < 2; jj++) {
                    int j = ng * 2 + jj;
                    mma16816(oacc[j], aph, &bvh[jj * 2]);
                    mma16816(oacc[j], aph, &bvl[jj * 2]);
                    mma16816(oacc[j], apl, &bvh[jj * 2]);
                }
            }
        }
        __syncthreads();
    }

    float inv0 = 1.f / l_[0], inv1 = 1.f / l_[1];
    #pragma unroll
    for (int j = 0; j < 16; j++)
        #pragma unroll
        for (int r = 0; r < 4; r++) {
            int t = m0 + qrow_lo + (r >> 1) * 8;
            int col = 8 * j + 2 * (lane & 3) + (r & 1);
            float v = oacc[j][r] * ((r >> 1) ? inv1 : inv0);
            size_t idx = ((size_t)(b * TT) + t) * DD + h * DHD + col;
            __nv_bfloat16 hv = __float2bfloat16(v);
            g_ahi[idx] = hv;
            g_alo[idx] = __float2bfloat16(v - __bfloat162float(hv));
        }
}

// ================= EMA (chunked parallel scan) =================
__global__ void ema_pass1(const float* __restrict__ x) {
    int idx = blockIdx.x * blockDim.x + threadIdx.x;
    int d = idx % DD;
    int c = (idx / DD) % NC;
    int b = idx / (DD * NC);
    const float beta = 0.9f, om = 1.0f - 0.9f;
    size_t base = ((size_t)b * TT + (size_t)c * LCH) * DD + d;
    float s = 0.f;
    #pragma unroll 4
    for (int p = 0; p < LCH; p++) {
        s = beta * s + om * x[base + (size_t)p * DD];
        g_l2[base + (size_t)p * DD] = s;
    }
    g_fin[c * BD + b * DD + d] = s;
}
__global__ void ema_pass2() {
    int idx = blockIdx.x * blockDim.x + threadIdx.x;
    const float bl = __powf(0.9f, (float)LCH);
    float P = 0.f;
    g_carry[idx] = 0.f;
    for (int c = 1; c < NC; c++) {
        P = g_fin[(c - 1) * BD + idx] + bl * P;
        g_carry[c * BD + idx] = P;
    }
}

// ================= router + level fusion (emit bf16 hi/lo) =================
__global__ void router_fuse(const float* __restrict__ x,
                            const float* __restrict__ l3mem,
                            const float* __restrict__ rw2,
                            const float* __restrict__ rb2,
                            float* __restrict__ lam_out) {
    int r = blockIdx.x;
    int tid = threadIdx.x;
    int b = r / TT, t = r % TT;
    const float* hrow = g_hdn + (size_t)r * DHALF;

    float p0 = 0.f, p1 = 0.f, p2 = 0.f;
    for (int j = tid; j < DHALF; j += 256) {
        float h = hrow[j];
        p0 = fmaf(h, rw2[j], p0);
        p1 = fmaf(h, rw2[DHALF + j], p1);
        p2 = fmaf(h, rw2[2 * DHALF + j], p2);
    }
    #pragma unroll
    for (int o = 16; o; o >>= 1) {
        p0 += __shfl_xor_sync(0xffffffffu, p0, o);
        p1 += __shfl_xor_sync(0xffffffffu, p1, o);
        p2 += __shfl_xor_sync(0xffffffffu, p2, o);
    }
    __shared__ float red0[8], red1[8], red2[8];
    __shared__ float lam[3];
    int lane = tid & 31, w = tid >> 5;
    if (lane == 0) { red0[w] = p0; red1[w] = p1; red2[w] = p2; }
    __syncthreads();
    if (tid == 0) {
        float l0 = rb2[0], l1 = rb2[1], l2v = rb2[2];
        #pragma unroll
        for (int ww = 0; ww < 8; ww++) { l0 += red0[ww]; l1 += red1[ww]; l2v += red2[ww]; }
        float mx = fmaxf(l0, fmaxf(l1, l2v));
        float e0 = expf(l0 - mx), e1 = expf(l1 - mx), e2 = expf(l2v - mx);
        float inv = 1.f / (e0 + e1 + e2);
        lam[0] = e0 * inv; lam[1] = e1 * inv; lam[2] = e2 * inv;
        lam_out[r * 3 + 0] = lam[0];
        lam_out[r * 3 + 1] = lam[1];
        lam_out[r * 3 + 2] = lam[2];
    }
    __syncthreads();
    float la = lam[0], lb = lam[1], lcc = lam[2];

    int c = t / LCH, p = t % LCH;
    float pb = __powf(0.9f, (float)(p + 1));
    const float* carr = g_carry + c * BD + b * DD;
    size_t ro = (size_t)r * DD;
    for (int j = tid; j < DD; j += 256) {
        float l2v = g_l2[ro + j] + pb * carr[j];
        float v = la * x[ro + j] + lb * l2v + lcc * l3mem[b * DD + j];
        __nv_bfloat16 hv = __float2bfloat16(v);
        g_fhi[ro + j] = hv;
        g_flo[ro + j] = __float2bfloat16(v - __bfloat162float(hv));
    }
}

// ================= launch =================
extern "C" void kernel_launch(void* const* d_in, const int* in_sizes, int n_in,
                              void* d_out, int out_size) {
    (void)in_sizes; (void)n_in; (void)out_size;
    const float* x    = (const float*)d_in[0];
    const float* l3m  = (const float*)d_in[1];
    const float* wq   = (const float*)d_in[2];
    const float* wk   = (const float*)d_in[3];
    const float* wv   = (const float*)d_in[4];
    const float* wo   = (const float*)d_in[5];
    const float* rw1  = (const float*)d_in[6];
    const float* rb1  = (const float*)d_in[7];
    const float* rw2  = (const float*)d_in[8];
    const float* rb2  = (const float*)d_in[9];

    float* out     = (float*)d_out;
    float* kh_out  = out + (size_t)RR * DD;
    float* vh_out  = kh_out + (size_t)RR * DD;
    float* lam_out = vh_out + (size_t)RR * DD;

    float* hdn_;
    cudaGetSymbolAddress((void**)&hdn_, g_hdn);

    __nv_bfloat16 *xhi,*xlo,*qhi,*qlo,*fhi,*flo,*ahi,*alo,*khhi,*khlo,*vhhi,*vhlo;
    __nv_bfloat16 *wqh,*wql,*wkh,*wkl,*wvh,*wvl,*woh,*wol,*r1h,*r1l;
    cudaGetSymbolAddress((void**)&xhi, g_xhi);  cudaGetSymbolAddress((void**)&xlo, g_xlo);
    cudaGetSymbolAddress((void**)&qhi, g_qhi);  cudaGetSymbolAddress((void**)&qlo, g_qlo);
    cudaGetSymbolAddress((void**)&fhi, g_fhi);  cudaGetSymbolAddress((void**)&flo, g_flo);
    cudaGetSymbolAddress((void**)&ahi, g_ahi);  cudaGetSymbolAddress((void**)&alo, g_alo);
    cudaGetSymbolAddress((void**)&khhi, g_khhi); cudaGetSymbolAddress((void**)&khlo, g_khlo);
    cudaGetSymbolAddress((void**)&vhhi, g_vhhi); cudaGetSymbolAddress((void**)&vhlo, g_vhlo);
    cudaGetSymbolAddress((void**)&wqh, g_wqhi); cudaGetSymbolAddress((void**)&wql, g_wqlo);
    cudaGetSymbolAddress((void**)&wkh, g_wkhi); cudaGetSymbolAddress((void**)&wkl, g_wklo);
    cudaGetSymbolAddress((void**)&wvh, g_wvhi); cudaGetSymbolAddress((void**)&wvl, g_wvlo);
    cudaGetSymbolAddress((void**)&woh, g_wohi); cudaGetSymbolAddress((void**)&wol, g_wolo);
    cudaGetSymbolAddress((void**)&r1h, g_r1hi); cudaGetSymbolAddress((void**)&r1l, g_r1lo);

    cudaFuncSetAttribute(gemm_mma<0>, cudaFuncAttributeMaxDynamicSharedMemorySize, SMEM_GEMM);
    cudaFuncSetAttribute(gemm_mma<1>, cudaFuncAttributeMaxDynamicSharedMemorySize, SMEM_GEMM);
    cudaFuncSetAttribute(gemm_mma<4>, cudaFuncAttributeMaxDynamicSharedMemorySize, SMEM_GEMM);
    cudaFuncSetAttribute(gemm_mma<5>, cudaFuncAttributeMaxDynamicSharedMemorySize, SMEM_GEMM);
    cudaFuncSetAttribute(flash_attn,  cudaFuncAttributeMaxDynamicSharedMemorySize, SMEM_FLASH);

    const int NBIG = RR * DD / 4;
    const int NR1  = DHALF * DD / 4;

    // merged hi/lo splits of x + all weights
    CvtArgs ca;
    ca.src[0] = (const float4*)x;   ca.hi[0] = (__nv_bfloat162*)xhi; ca.lo[0] = (__nv_bfloat162*)xlo; ca.n4[0] = NBIG;
    ca.src[1] = (const float4*)wq;  ca.hi[1] = (__nv_bfloat162*)wqh; ca.lo[1] = (__nv_bfloat162*)wql; ca.n4[1] = NBIG;
    ca.src[2] = (const float4*)wk;  ca.hi[2] = (__nv_bfloat162*)wkh; ca.lo[2] = (__nv_bfloat162*)wkl; ca.n4[2] = NBIG;
    ca.src[3] = (const float4*)wv;  ca.hi[3] = (__nv_bfloat162*)wvh; ca.lo[3] = (__nv_bfloat162*)wvl; ca.n4[3] = NBIG;
    ca.src[4] = (const float4*)wo;  ca.hi[4] = (__nv_bfloat162*)woh; ca.lo[4] = (__nv_bfloat162*)wol; ca.n4[4] = NBIG;
    ca.src[5] = (const float4*)rw1; ca.hi[5] = (__nv_bfloat162*)r1h; ca.lo[5] = (__nv_bfloat162*)r1l; ca.n4[5] = NR1;
    cvt_split_all<<<dim3(NBIG/256, 6), 256>>>(ca);

    ema_pass1<<<BB * NC * DD / 256, 256>>>(x);
    ema_pass2<<<BD / 256, 256>>>();

    // q (bf16 hi/lo direct)
    gemm_mma<4><<<dim3(DD/128, RR/64), 128, SMEM_GEMM>>>(xhi, xlo, wqh, wql, nullptr, qhi, qlo, DD, nullptr);
    // hdn = silu(q @ rw1^T + rb1)
    gemm_mma<1><<<dim3(DHALF/128, RR/64), 128, SMEM_GEMM>>>(qhi, qlo, r1h, r1l, hdn_, nullptr, nullptr, DHALF, rb1);
    // router + fuse (emits fhi/flo)
    router_fuse<<<RR, 256>>>(x, l3m, rw2, rb2, lam_out);
    // K/V: fp32 head-layout outputs + bf16 hi/lo head layout
    gemm_mma<5><<<dim3(DD/128, RR/64), 128, SMEM_GEMM>>>(fhi, flo, wkh, wkl, kh_out, khhi, khlo, 0, nullptr);
    gemm_mma<5><<<dim3(DD/128, RR/64), 128, SMEM_GEMM>>>(fhi, flo, wvh, wvl, vh_out, vhhi, vhlo, 0, nullptr);
    // fused attention
    flash_attn<<<dim3(BB*HH, TT/128), 256, SMEM_FLASH>>>(khhi, khlo, vhhi, vhlo);
    // out = attno @ wo^T
    gemm_mma<0><<<dim3(DD/128, RR/64), 128, SMEM_GEMM>>>(ahi, alo, woh, wol, out, nullptr, nullptr, DD, nullptr);
}

// round 13
// speedup vs baseline: 1.2408x; 1.2408x over previous
#include <cuda_runtime.h>
#include <cuda_bf16.h>
#include <math.h>
#include <stdint.h>

// Problem constants
#define BB 2
#define TT 1024
#define DD 2048
#define HH 16
#define DHD 128
#define RR (BB*TT)       // 2048
#define DHALF (DD/2)     // 1024
#define LCH 128
#define NC (TT/LCH)
#define BD (BB*DD)

#define KDIM 2048
#define NCHUNK (KDIM/64)                      // 32 chunks of 64 bf16
#define STAGE_BYTES 49152                     // A hi/lo 8K+8K, B hi/lo 16K+16K
#define SMEM_GEMM (2*STAGE_BYTES + 1024)      // 97KB -> 2 CTAs/SM
#define SMEM_FLASH (65536 + 2*65536 + 1024)   // Q + 2 KV stages

// -------- fp32 scratch --------
__device__ float g_hdn[RR*DHALF];
__device__ float g_l2[RR*DD];
__device__ float g_fin[NC*BD];
__device__ float g_carry[NC*BD];

// -------- bf16 hi/lo scratch --------
__device__ __nv_bfloat16 g_xhi[RR*DD],  g_xlo[RR*DD];
__device__ __nv_bfloat16 g_qhi[RR*DD],  g_qlo[RR*DD];
__device__ __nv_bfloat16 g_fhi[RR*DD],  g_flo[RR*DD];
__device__ __nv_bfloat16 g_ahi[RR*DD],  g_alo[RR*DD];
__device__ __nv_bfloat16 g_khhi[RR*DD], g_khlo[RR*DD];   // [b,h,t,dh]
__device__ __nv_bfloat16 g_vhhi[RR*DD], g_vhlo[RR*DD];   // [b,h,t,dh]
__device__ __nv_bfloat16 g_wqhi[DD*DD], g_wqlo[DD*DD];
__device__ __nv_bfloat16 g_wkhi[DD*DD], g_wklo[DD*DD];
__device__ __nv_bfloat16 g_wvhi[DD*DD], g_wvlo[DD*DD];
__device__ __nv_bfloat16 g_wohi[DD*DD], g_wolo[DD*DD];
__device__ __nv_bfloat16 g_r1hi[DHALF*DD], g_r1lo[DHALF*DD];

// ================= PTX helpers =================
__device__ __forceinline__ uint32_t smem_u32(const void* p) {
    uint32_t a;
    asm("{ .reg .u64 t; cvta.to.shared.u64 t, %1; cvt.u32.u64 %0, t; }" : "=r"(a) : "l"(p));
    return a;
}
__device__ __forceinline__ void cpasync16(uint32_t s, const void* g) {
    asm volatile("cp.async.cg.shared.global [%0], [%1], 16;" :: "r"(s), "l"(g));
}
#define CP_COMMIT() asm volatile("cp.async.commit_group;" ::: "memory")
#define CP_WAIT(n)  asm volatile("cp.async.wait_group %0;" :: "n"(n) : "memory")

__device__ __forceinline__ void ldsm4(uint32_t* r, uint32_t addr) {
    asm volatile("ldmatrix.sync.aligned.m8n8.x4.shared.b16 {%0,%1,%2,%3}, [%4];"
        : "=r"(r[0]), "=r"(r[1]), "=r"(r[2]), "=r"(r[3]) : "r"(addr));
}
__device__ __forceinline__ void ldsm4t(uint32_t* r, uint32_t addr) {
    asm volatile("ldmatrix.sync.aligned.m8n8.x4.trans.shared.b16 {%0,%1,%2,%3}, [%4];"
        : "=r"(r[0]), "=r"(r[1]), "=r"(r[2]), "=r"(r[3]) : "r"(addr));
}
__device__ __forceinline__ void mma16816(float* c, const uint32_t* a, const uint32_t* b) {
    asm volatile(
        "mma.sync.aligned.m16n8k16.row.col.f32.bf16.bf16.f32 "
        "{%0,%1,%2,%3}, {%4,%5,%6,%7}, {%8,%9}, {%0,%1,%2,%3};"
        : "+f"(c[0]), "+f"(c[1]), "+f"(c[2]), "+f"(c[3])
        : "r"(a[0]), "r"(a[1]), "r"(a[2]), "r"(a[3]), "r"(b[0]), "r"(b[1]));
}
__device__ __forceinline__ void pack_hilo(float x, float y, uint32_t& hi, uint32_t& lo) {
    __nv_bfloat16 hx = __float2bfloat16(x), hy = __float2bfloat16(y);
    __nv_bfloat16 lx = __float2bfloat16(x - __bfloat162float(hx));
    __nv_bfloat16 ly = __float2bfloat16(y - __bfloat162float(hy));
    __nv_bfloat162 hp(hx, hy), lp(lx, ly);
    hi = *(uint32_t*)&hp; lo = *(uint32_t*)&lp;
}

// ================= fp32 -> bf16 hi/lo split (merged, 6 tensors) ============
struct CvtArgs {
    const float4* src[6];
    __nv_bfloat162* hi[6];
    __nv_bfloat162* lo[6];
    int n4[6];
};
__global__ void cvt_split_all(CvtArgs a) {
    int t = blockIdx.y;
    int i = blockIdx.x * blockDim.x + threadIdx.x;
    if (i >= a.n4[t]) return;
    float4 v = a.src[t][i];
    __nv_bfloat16 h0 = __float2bfloat16(v.x), h1 = __float2bfloat16(v.y);
    __nv_bfloat16 h2 = __float2bfloat16(v.z), h3 = __float2bfloat16(v.w);
    __nv_bfloat16 l0 = __float2bfloat16(v.x - __bfloat162float(h0));
    __nv_bfloat16 l1 = __float2bfloat16(v.y - __bfloat162float(h1));
    __nv_bfloat16 l2 = __float2bfloat16(v.z - __bfloat162float(h2));
    __nv_bfloat16 l3 = __float2bfloat16(v.w - __bfloat162float(h3));
    a.hi[t][2*i]   = __nv_bfloat162(h0, h1);
    a.hi[t][2*i+1] = __nv_bfloat162(h2, h3);
    a.lo[t][2*i]   = __nv_bfloat162(l0, l1);
    a.lo[t][2*i+1] = __nv_bfloat162(l2, l3);
}

// ================= HMMA GEMM: C = A * B^T (split bf16, fp32 acc) ===========
// 64x128 CTA tile, 128 threads (2x2 warps of 32x64), BK=64, 2-stage pipeline,
// 2 CTAs/SM. Vectorized epilogue (float2 / packed-uint32 stores).
// MODE 0: fp32 plain   MODE 1: bias+silu fp32
// MODE 4: bf16 hi/lo plain   MODE 5: fp32 scatter + bf16 hi/lo scatter [b,h,t,dh]
template<int MODE>
__global__ void __launch_bounds__(128, 2)
gemm_mma(const __nv_bfloat16* __restrict__ Ahi, const __nv_bfloat16* __restrict__ Alo,
         const __nv_bfloat16* __restrict__ Bhi, const __nv_bfloat16* __restrict__ Blo,
         float* __restrict__ C, __nv_bfloat16* __restrict__ Chi,
         __nv_bfloat16* __restrict__ Clo, int ldc, const float* __restrict__ bias) {
    extern __shared__ char dsm[];
    const int tid  = threadIdx.x;
    const int wid  = tid >> 5, lane = tid & 31;
    const int m0   = blockIdx.y * 64, n0 = blockIdx.x * 128;
    const int wm   = (wid & 1) * 32;
    const int wn   = (wid >> 1) * 64;
    uint32_t sb = (smem_u32(dsm) + 1023u) & ~1023u;

    const char* gA0 = (const char*)(Ahi + (size_t)m0 * KDIM);
    const char* gA1 = (const char*)(Alo + (size_t)m0 * KDIM);
    const char* gB0 = (const char*)(Bhi + (size_t)n0 * KDIM);
    const char* gB1 = (const char*)(Blo + (size_t)n0 * KDIM);

    // stage layout: Ahi@0(8K) Alo@8K Bhi@16K(16K) Blo@32K(16K)
    auto load_stage = [&](int s, int k0) {
        uint32_t base = sb + (uint32_t)s * STAGE_BYTES;
        const int kb = k0 * 2;   // byte offset in K
        #pragma unroll
        for (int it = 0; it < 4; it++) {
            int idx = tid + it * 128;                  // 0..511
            int m = idx >> 3, j = idx & 7;
            uint32_t off = (uint32_t)m * 128u + (uint32_t)((j ^ (m & 7)) << 4);
            size_t go = (size_t)m * (KDIM * 2) + kb + j * 16;
            cpasync16(base + off,         gA0 + go);
            cpasync16(base + 8192u + off, gA1 + go);
        }
        #pragma unroll
        for (int it = 0; it < 8; it++) {
            int idx = tid + it * 128;                  // 0..1023
            int m = idx >> 3, j = idx & 7;
            uint32_t off = (uint32_t)m * 128u + (uint32_t)((j ^ (m & 7)) << 4);
            size_t go = (size_t)m * (KDIM * 2) + kb + j * 16;
            cpasync16(base + 16384u + off, gB0 + go);
            cpasync16(base + 32768u + off, gB1 + go);
        }
        CP_COMMIT();
    };

    float acc[2][8][4];
    #pragma unroll
    for (int i = 0; i < 2; i++)
        #pragma unroll
        for (int j = 0; j < 8; j++)
            #pragma unroll
            for (int r = 0; r < 4; r++) acc[i][j][r] = 0.f;

    const int aRow0 = wm + ((lane >> 3) & 1) * 8 + (lane & 7);
    const int aKh   = (lane >> 4) & 1;
    const int bRow0 = wn + ((lane >> 4) & 1) * 8 + (lane & 7);
    const int bKh   = (lane >> 3) & 1;

    load_stage(0, 0);
    load_stage(1, 64);

    #pragma unroll 1
    for (int c = 0; c < NCHUNK; c++) {
        if (c + 2 < NCHUNK) { CP_WAIT(1); } else { CP_WAIT(0); }
        __syncthreads();

        uint32_t base = sb + (uint32_t)(c & 1) * STAGE_BYTES;
        #pragma unroll
        for (int kk = 0; kk < 4; kk++) {
            uint32_t ah[2][4], al[2][4], bh[4][4], bl[4][4];
            #pragma unroll
            for (int mt = 0; mt < 2; mt++) {
                int row = aRow0 + mt * 16;
                int cc = (kk * 2 + aKh) ^ (row & 7);
                uint32_t off = (uint32_t)row * 128u + (uint32_t)cc * 16u;
                ldsm4(ah[mt], base + off);
                ldsm4(al[mt], base + 8192u + off);
            }
            #pragma unroll
            for (int g = 0; g < 4; g++) {
                int row = bRow0 + g * 16;
                int cc = (kk * 2 + bKh) ^ (row & 7);
                uint32_t off = (uint32_t)row * 128u + (uint32_t)cc * 16u;
                ldsm4(bh[g], base + 16384u + off);
                ldsm4(bl[g], base + 32768u + off);
            }
            #pragma unroll
            for (int i = 0; i < 2; i++)
                #pragma unroll
                for (int j = 0; j < 8; j++) {
                    const uint32_t* bph = &bh[j >> 1][(j & 1) * 2];
                    const uint32_t* bpl = &bl[j >> 1][(j & 1) * 2];
                    mma16816(acc[i][j], ah[i], bph);
                    mma16816(acc[i][j], ah[i], bpl);
                    mma16816(acc[i][j], al[i], bph);
                }
        }
        __syncthreads();
        if (c + 2 < NCHUNK) load_stage(c & 1, (c + 2) * 64);
    }

    // ---- vectorized epilogue: r-pairs are adjacent even columns ----
    #pragma unroll
    for (int i = 0; i < 2; i++) {
        #pragma unroll
        for (int j = 0; j < 8; j++) {
            #pragma unroll
            for (int rr = 0; rr < 2; rr++) {
                int row = m0 + wm + i * 16 + (lane >> 2) + rr * 8;
                int col = n0 + wn + j * 8 + (lane & 3) * 2;
                float v0 = acc[i][j][rr * 2 + 0];
                float v1 = acc[i][j][rr * 2 + 1];
                if (MODE == 0) {
                    *(float2*)(C + (size_t)row * ldc + col) = make_float2(v0, v1);
                } else if (MODE == 1) {
                    v0 += bias[col];     v1 += bias[col + 1];
                    v0 = v0 / (1.f + expf(-v0));
                    v1 = v1 / (1.f + expf(-v1));
                    *(float2*)(C + (size_t)row * ldc + col) = make_float2(v0, v1);
                } else if (MODE == 4) {
                    size_t idx = (size_t)row * ldc + col;
                    uint32_t hp, lp; pack_hilo(v0, v1, hp, lp);
                    *(uint32_t*)(Chi + idx) = hp;
                    *(uint32_t*)(Clo + idx) = lp;
                } else {  // MODE 5
                    int b = row >> 10, t = row & 1023;
                    int h = col >> 7,  jj = col & 127;
                    size_t idx = (((size_t)(b * HH + h)) * TT + t) * DHD + jj;
                    *(float2*)(C + idx) = make_float2(v0, v1);
                    uint32_t hp, lp; pack_hilo(v0, v1, hp, lp);
                    *(uint32_t*)(Chi + idx) = hp;
                    *(uint32_t*)(Clo + idx) = lp;
                }
            }
        }
    }
}

// ================= flash attention (fused S, softmax, PV) ==================
__global__ void __launch_bounds__(256, 1)
flash_attn(const __nv_bfloat16* __restrict__ khhi, const __nv_bfloat16* __restrict__ khlo,
           const __nv_bfloat16* __restrict__ vhhi, const __nv_bfloat16* __restrict__ vhlo) {
    extern __shared__ char dsm[];
    const int z  = blockIdx.x;
    const int qi = (int)gridDim.y - 1 - (int)blockIdx.y;
    const int b = z >> 4, h = z & 15;
    const int m0 = qi * 128;
    const int tid = threadIdx.x, wid = tid >> 5, lane = tid & 31;
    uint32_t sb = (smem_u32(dsm) + 1023u) & ~1023u;
    const uint32_t qs = sb;

    {
        const __nv_bfloat16* Qh = g_qhi + ((size_t)(b * TT) + m0) * DD + h * DHD;
        const __nv_bfloat16* Ql = g_qlo + ((size_t)(b * TT) + m0) * DD + h * DHD;
        #pragma unroll
        for (int it = 0; it < 8; it++) {
            int idx = tid + it * 256;
            int row = idx >> 4, u = idx & 15;
            uint32_t sa = qs + (uint32_t)row * 256u + (uint32_t)((u ^ (row & 7)) << 4);
            cpasync16(sa,           Qh + (size_t)row * DD + u * 8);
            cpasync16(sa + 32768u,  Ql + (size_t)row * DD + u * 8);
        }
    }
    const __nv_bfloat16* Kh = khhi + (size_t)z * TT * DHD;
    const __nv_bfloat16* Kl = khlo + (size_t)z * TT * DHD;
    const __nv_bfloat16* Vh = vhhi + (size_t)z * TT * DHD;
    const __nv_bfloat16* Vl = vhlo + (size_t)z * TT * DHD;

    auto load_kv = [&](int s, int ch) {
        uint32_t base = sb + 65536u + (uint32_t)s * 65536u;
        const __nv_bfloat16* srcs[4] = {
            Kh + (size_t)ch * 64 * DHD, Kl + (size_t)ch * 64 * DHD,
            Vh + (size_t)ch * 64 * DHD, Vl + (size_t)ch * 64 * DHD };
        #pragma unroll
        for (int tI = 0; tI < 4; tI++) {
            uint32_t tb = base + (uint32_t)tI * 16384u;
            const __nv_bfloat16* g = srcs[tI];
            #pragma unroll
            for (int it = 0; it < 4; it++) {
                int idx = tid + it * 256;
                int row = idx >> 4, u = idx & 15;
                cpasync16(tb + (uint32_t)row * 256u + (uint32_t)((u ^ (row & 7)) << 4),
                          g + (size_t)row * DHD + u * 8);
            }
        }
        CP_COMMIT();
    };

    const int nch = 2 * qi + 2;
    load_kv(0, 0);

    float m_[2] = {-1e30f, -1e30f}, l_[2] = {0.f, 0.f};
    float oacc[16][4];
    #pragma unroll
    for (int j = 0; j < 16; j++)
        #pragma unroll
        for (int r = 0; r < 4; r++) oacc[j][r] = 0.f;

    const int qrow_lo = wid * 16 + (lane >> 2);
    const float scale = 0.08838834764831845f;

    #pragma unroll 1
    for (int ch = 0; ch < nch; ch++) {
        if (ch + 1 < nch) {
            load_kv((ch + 1) & 1, ch + 1);
            CP_WAIT(1);
        } else {
            CP_WAIT(0);
        }
        __syncthreads();
        uint32_t kb = sb + 65536u + (uint32_t)(ch & 1) * 65536u;
        uint32_t vb = kb + 32768u;

        float sacc[8][4];
        #pragma unroll
        for (int j = 0; j < 8; j++)
            #pragma unroll
            for (int r = 0; r < 4; r++) sacc[j][r] = 0.f;

        #pragma unroll
        for (int kk = 0; kk < 8; kk++) {
            uint32_t ah[4], al[4];
            int arow = wid * 16 + ((lane >> 3) & 1) * 8 + (lane & 7);
            int au = (kk * 2 + ((lane >> 4) & 1)) ^ (arow & 7);
            uint32_t aoff = (uint32_t)arow * 256u + (uint32_t)au * 16u;
            ldsm4(ah, qs + aoff);
            ldsm4(al, qs + 32768u + aoff);
            #pragma unroll
            for (int g = 0; g < 4; g++) {
                uint32_t bh_[4], bl_[4];
                int brow = g * 16 + ((lane >> 4) & 1) * 8 + (lane & 7);
                int bu = (kk * 2 + ((lane >> 3) & 1)) ^ (brow & 7);
                uint32_t boff = (uint32_t)brow * 256u + (uint32_t)bu * 16u;
                ldsm4(bh_, kb + boff);
                ldsm4(bl_, kb + 16384u + boff);
                #pragma unroll
                for (int jj = 0; jj < 2; jj++) {
                    int j = g * 2 + jj;
                    mma16816(sacc[j], ah, &bh_[jj * 2]);
                    mma16816(sacc[j], ah, &bl_[jj * 2]);
                    mma16816(sacc[j], al, &bh_[jj * 2]);
                }
            }
        }

        const int kvbase = ch * 64;
        const bool maskp = (kvbase + 63 > m0);
        float mx[2] = {-1e30f, -1e30f};
        #pragma unroll
        for (int j = 0; j < 8; j++)
            #pragma unroll
            for (int r = 0; r < 4; r++) {
                float v = sacc[j][r] * scale;
                if (maskp) {
                    int col_g = kvbase + 8 * j + 2 * (lane & 3) + (r & 1);
                    int row_g = m0 + qrow_lo + (r >> 1) * 8;
                    if (col_g > row_g) v = -1e30f;
                }
                sacc[j][r] = v;
                mx[r >> 1] = fmaxf(mx[r >> 1], v);
            }
        #pragma unroll
        for (int rr = 0; rr < 2; rr++) {
            mx[rr] = fmaxf(mx[rr], __shfl_xor_sync(0xffffffffu, mx[rr], 1));
            mx[rr] = fmaxf(mx[rr], __shfl_xor_sync(0xffffffffu, mx[rr], 2));
        }
        float mn0 = fmaxf(m_[0], mx[0]), mn1 = fmaxf(m_[1], mx[1]);
        float al0 = __expf(m_[0] - mn0), al1 = __expf(m_[1] - mn1);
        float rs[2] = {0.f, 0.f};
        #pragma unroll
        for (int j = 0; j < 8; j++)
            #pragma unroll
            for (int r = 0; r < 4; r++) {
                float p = __expf(sacc[j][r] - ((r >> 1) ? mn1 : mn0));
                sacc[j][r] = p;
                rs[r >> 1] += p;
            }
        #pragma unroll
        for (int rr = 0; rr < 2; rr++) {
            rs[rr] += __shfl_xor_sync(0xffffffffu, rs[rr], 1);
            rs[rr] += __shfl_xor_sync(0xffffffffu, rs[rr], 2);
        }
        l_[0] = l_[0] * al0 + rs[0];
        l_[1] = l_[1] * al1 + rs[1];
        m_[0] = mn0; m_[1] = mn1;
        #pragma unroll
        for (int j = 0; j < 16; j++) {
            oacc[j][0] *= al0; oacc[j][1] *= al0;
            oacc[j][2] *= al1; oacc[j][3] *= al1;
        }

        #pragma unroll
        for (int kk = 0; kk < 4; kk++) {
            uint32_t aph[4], apl[4];
            pack_hilo(sacc[2*kk][0],   sacc[2*kk][1],   aph[0], apl[0]);
            pack_hilo(sacc[2*kk][2],   sacc[2*kk][3],   aph[1], apl[1]);
            pack_hilo(sacc[2*kk+1][0], sacc[2*kk+1][1], aph[2], apl[2]);
            pack_hilo(sacc[2*kk+1][2], sacc[2*kk+1][3], aph[3], apl[3]);
            int krow = kk * 16 + ((lane >> 3) & 1) * 8 + (lane & 7);
            #pragma unroll
            for (int ng = 0; ng < 8; ng++) {
                int nchk = ng * 2 + (lane >> 4);
                uint32_t addr = vb + (uint32_t)krow * 256u
                              + (uint32_t)((nchk ^ (krow & 7)) << 4);
                uint32_t bvh[4], bvl[4];
                ldsm4t(bvh, addr);
                ldsm4t(bvl, addr + 16384u);
                #pragma unroll
                for (int jj = 0; jj < 2; jj++) {
                    int j = ng * 2 + jj;
                    mma16816(oacc[j], aph, &bvh[jj * 2]);
                    mma16816(oacc[j], aph, &bvl[jj * 2]);
                    mma16816(oacc[j], apl, &bvh[jj * 2]);
                }
            }
        }
        __syncthreads();
    }

    float inv0 = 1.f / l_[0], inv1 = 1.f / l_[1];
    #pragma unroll
    for (int j = 0; j < 16; j++)
        #pragma unroll
        for (int rr = 0; rr < 2; rr++) {
            int t = m0 + qrow_lo + rr * 8;
            int col = 8 * j + 2 * (lane & 3);
            float inv = rr ? inv1 : inv0;
            float v0 = oacc[j][rr * 2 + 0] * inv;
            float v1 = oacc[j][rr * 2 + 1] * inv;
            size_t idx = ((size_t)(b * TT) + t) * DD + h * DHD + col;
            uint32_t hp, lp; pack_hilo(v0, v1, hp, lp);
            *(uint32_t*)(g_ahi + idx) = hp;
            *(uint32_t*)(g_alo + idx) = lp;
        }
}

// ================= EMA (chunked parallel scan) =================
__global__ void ema_pass1(const float* __restrict__ x) {
    int idx = blockIdx.x * blockDim.x + threadIdx.x;
    int d = idx % DD;
    int c = (idx / DD) % NC;
    int b = idx / (DD * NC);
    const float beta = 0.9f, om = 1.0f - 0.9f;
    size_t base = ((size_t)b * TT + (size_t)c * LCH) * DD + d;
    float s = 0.f;
    #pragma unroll 4
    for (int p = 0; p < LCH; p++) {
        s = beta * s + om * x[base + (size_t)p * DD];
        g_l2[base + (size_t)p * DD] = s;
    }
    g_fin[c * BD + b * DD + d] = s;
}
__global__ void ema_pass2() {
    int idx = blockIdx.x * blockDim.x + threadIdx.x;
    const float bl = __powf(0.9f, (float)LCH);
    float P = 0.f;
    g_carry[idx] = 0.f;
    for (int c = 1; c < NC; c++) {
        P = g_fin[(c - 1) * BD + idx] + bl * P;
        g_carry[c * BD + idx] = P;
    }
}

// ================= router + level fusion (emit bf16 hi/lo) =================
__global__ void router_fuse(const float* __restrict__ x,
                            const float* __restrict__ l3mem,
                            const float* __restrict__ rw2,
                            const float* __restrict__ rb2,
                            float* __restrict__ lam_out) {
    int r = blockIdx.x;
    int tid = threadIdx.x;
    int b = r / TT, t = r % TT;
    const float* hrow = g_hdn + (size_t)r * DHALF;

    float p0 = 0.f, p1 = 0.f, p2 = 0.f;
    for (int j = tid; j < DHALF; j += 256) {
        float h = hrow[j];
        p0 = fmaf(h, rw2[j], p0);
        p1 = fmaf(h, rw2[DHALF + j], p1);
        p2 = fmaf(h, rw2[2 * DHALF + j], p2);
    }
    #pragma unroll
    for (int o = 16; o; o >>= 1) {
        p0 += __shfl_xor_sync(0xffffffffu, p0, o);
        p1 += __shfl_xor_sync(0xffffffffu, p1, o);
        p2 += __shfl_xor_sync(0xffffffffu, p2, o);
    }
    __shared__ float red0[8], red1[8], red2[8];
    __shared__ float lam[3];
    int lane = tid & 31, w = tid >> 5;
    if (lane == 0) { red0[w] = p0; red1[w] = p1; red2[w] = p2; }
    __syncthreads();
    if (tid == 0) {
        float l0 = rb2[0], l1 = rb2[1], l2v = rb2[2];
        #pragma unroll
        for (int ww = 0; ww < 8; ww++) { l0 += red0[ww]; l1 += red1[ww]; l2v += red2[ww]; }
        float mx = fmaxf(l0, fmaxf(l1, l2v));
        float e0 = expf(l0 - mx), e1 = expf(l1 - mx), e2 = expf(l2v - mx);
        float inv = 1.f / (e0 + e1 + e2);
        lam[0] = e0 * inv; lam[1] = e1 * inv; lam[2] = e2 * inv;
        lam_out[r * 3 + 0] = lam[0];
        lam_out[r * 3 + 1] = lam[1];
        lam_out[r * 3 + 2] = lam[2];
    }
    __syncthreads();
    float la = lam[0], lb = lam[1], lcc = lam[2];

    int c = t / LCH, p = t % LCH;
    float pb = __powf(0.9f, (float)(p + 1));
    const float* carr = g_carry + c * BD + b * DD;
    size_t ro = (size_t)r * DD;
    for (int j = tid; j < DD; j += 256) {
        float l2v = g_l2[ro + j] + pb * carr[j];
        float v = la * x[ro + j] + lb * l2v + lcc * l3mem[b * DD + j];
        __nv_bfloat16 hv = __float2bfloat16(v);
        g_fhi[ro + j] = hv;
        g_flo[ro + j] = __float2bfloat16(v - __bfloat162float(hv));
    }
}

// ================= launch =================
extern "C" void kernel_launch(void* const* d_in, const int* in_sizes, int n_in,
                              void* d_out, int out_size) {
    (void)in_sizes; (void)n_in; (void)out_size;
    const float* x    = (const float*)d_in[0];
    const float* l3m  = (const float*)d_in[1];
    const float* wq   = (const float*)d_in[2];
    const float* wk   = (const float*)d_in[3];
    const float* wv   = (const float*)d_in[4];
    const float* wo   = (const float*)d_in[5];
    const float* rw1  = (const float*)d_in[6];
    const float* rb1  = (const float*)d_in[7];
    const float* rw2  = (const float*)d_in[8];
    const float* rb2  = (const float*)d_in[9];

    float* out     = (float*)d_out;
    float* kh_out  = out + (size_t)RR * DD;
    float* vh_out  = kh_out + (size_t)RR * DD;
    float* lam_out = vh_out + (size_t)RR * DD;

    float* hdn_;
    cudaGetSymbolAddress((void**)&hdn_, g_hdn);

    __nv_bfloat16 *xhi,*xlo,*qhi,*qlo,*fhi,*flo,*ahi,*alo,*khhi,*khlo,*vhhi,*vhlo;
    __nv_bfloat16 *wqh,*wql,*wkh,*wkl,*wvh,*wvl,*woh,*wol,*r1h,*r1l;
    cudaGetSymbolAddress((void**)&xhi, g_xhi);  cudaGetSymbolAddress((void**)&xlo, g_xlo);
    cudaGetSymbolAddress((void**)&qhi, g_qhi);  cudaGetSymbolAddress((void**)&qlo, g_qlo);
    cudaGetSymbolAddress((void**)&fhi, g_fhi);  cudaGetSymbolAddress((void**)&flo, g_flo);
    cudaGetSymbolAddress((void**)&ahi, g_ahi);  cudaGetSymbolAddress((void**)&alo, g_alo);
    cudaGetSymbolAddress((void**)&khhi, g_khhi); cudaGetSymbolAddress((void**)&khlo, g_khlo);
    cudaGetSymbolAddress((void**)&vhhi, g_vhhi); cudaGetSymbolAddress((void**)&vhlo, g_vhlo);
    cudaGetSymbolAddress((void**)&wqh, g_wqhi); cudaGetSymbolAddress((void**)&wql, g_wqlo);
    cudaGetSymbolAddress((void**)&wkh, g_wkhi); cudaGetSymbolAddress((void**)&wkl, g_wklo);
    cudaGetSymbolAddress((void**)&wvh, g_wvhi); cudaGetSymbolAddress((void**)&wvl, g_wvlo);
    cudaGetSymbolAddress((void**)&woh, g_wohi); cudaGetSymbolAddress((void**)&wol, g_wolo);
    cudaGetSymbolAddress((void**)&r1h, g_r1hi); cudaGetSymbolAddress((void**)&r1l, g_r1lo);

    cudaFuncSetAttribute(gemm_mma<0>, cudaFuncAttributeMaxDynamicSharedMemorySize, SMEM_GEMM);
    cudaFuncSetAttribute(gemm_mma<1>, cudaFuncAttributeMaxDynamicSharedMemorySize, SMEM_GEMM);
    cudaFuncSetAttribute(gemm_mma<4>, cudaFuncAttributeMaxDynamicSharedMemorySize, SMEM_GEMM);
    cudaFuncSetAttribute(gemm_mma<5>, cudaFuncAttributeMaxDynamicSharedMemorySize, SMEM_GEMM);
    cudaFuncSetAttribute(flash_attn,  cudaFuncAttributeMaxDynamicSharedMemorySize, SMEM_FLASH);

    const int NBIG = RR * DD / 4;
    const int NR1  = DHALF * DD / 4;

    // merged hi/lo splits of x + all weights
    CvtArgs ca;
    ca.src[0] = (const float4*)x;   ca.hi[0] = (__nv_bfloat162*)xhi; ca.lo[0] = (__nv_bfloat162*)xlo; ca.n4[0] = NBIG;
    ca.src[1] = (const float4*)wq;  ca.hi[1] = (__nv_bfloat162*)wqh; ca.lo[1] = (__nv_bfloat162*)wql; ca.n4[1] = NBIG;
    ca.src[2] = (const float4*)wk;  ca.hi[2] = (__nv_bfloat162*)wkh; ca.lo[2] = (__nv_bfloat162*)wkl; ca.n4[2] = NBIG;
    ca.src[3] = (const float4*)wv;  ca.hi[3] = (__nv_bfloat162*)wvh; ca.lo[3] = (__nv_bfloat162*)wvl; ca.n4[3] = NBIG;
    ca.src[4] = (const float4*)wo;  ca.hi[4] = (__nv_bfloat162*)woh; ca.lo[4] = (__nv_bfloat162*)wol; ca.n4[4] = NBIG;
    ca.src[5] = (const float4*)rw1; ca.hi[5] = (__nv_bfloat162*)r1h; ca.lo[5] = (__nv_bfloat162*)r1l; ca.n4[5] = NR1;
    cvt_split_all<<<dim3(NBIG/256, 6), 256>>>(ca);

    ema_pass1<<<BB * NC * DD / 256, 256>>>(x);
    ema_pass2<<<BD / 256, 256>>>();

    // q (bf16 hi/lo direct)
    gemm_mma<4><<<dim3(DD/128, RR/64), 128, SMEM_GEMM>>>(xhi, xlo, wqh, wql, nullptr, qhi, qlo, DD, nullptr);
    // hdn = silu(q @ rw1^T + rb1)
    gemm_mma<1><<<dim3(DHALF/128, RR/64), 128, SMEM_GEMM>>>(qhi, qlo, r1h, r1l, hdn_, nullptr, nullptr, DHALF, rb1);
    // router + fuse (emits fhi/flo)
    router_fuse<<<RR, 256>>>(x, l3m, rw2, rb2, lam_out);
    // K/V: fp32 head-layout outputs + bf16 hi/lo head layout
    gemm_mma<5><<<dim3(DD/128, RR/64), 128, SMEM_GEMM>>>(fhi, flo, wkh, wkl, kh_out, khhi, khlo, 0, nullptr);
    gemm_mma<5><<<dim3(DD/128, RR/64), 128, SMEM_GEMM>>>(fhi, flo, wvh, wvl, vh_out, vhhi, vhlo, 0, nullptr);
    // fused attention
    flash_attn<<<dim3(BB*HH, TT/128), 256, SMEM_FLASH>>>(khhi, khlo, vhhi, vhlo);
    // out = attno @ wo^T
    gemm_mma<0><<<dim3(DD/128, RR/64), 128, SMEM_GEMM>>>(ahi, alo, woh, wol, out, nullptr, nullptr, DD, nullptr);
}